// round 12
// baseline (speedup 1.0000x reference)
#include <cuda_runtime.h>

#define HW 65536
#define IMW 256

// ------------------------- device scratch (no allocations) -------------------------
static __device__ __align__(16) float g_projT[128*128];
static __device__ __align__(16) float g_preT [64*64];
static __device__ __align__(16) float g_qkvT [3*64*64];   // chunk-major: [cc][k][64]
static __device__ __align__(16) float g_g1T  [64*32];
static __device__ __align__(16) float g_postT[64*64];
static __device__ __align__(16) float g_poutT[128*128];

static __device__ __align__(16) float g_lb  [(size_t)4*64*HW];   // local branch residual
static __device__ __align__(16) float g_xpre[(size_t)4*64*HW];   // lgce pre-conv output
static __device__ __align__(16) float g_qkv [(size_t)4*192*HW];  // qkv (pre-dwconv)
static __device__ __align__(16) float g_vd  [(size_t)4*64*HW];   // dwconv'd v

static __device__ double g_pooled[4*64];
static __device__ double g_gate_sum;
static __device__ double g_resp_sum[4*8];
static __device__ double g_gram[4*8*64];
static __device__ double g_qss[4*64];
static __device__ double g_kss[4*64];
static __device__ float  g_cw[4*64];
static __device__ float  g_kdyn;
static __device__ float  g_attnw[4*8*64];

__device__ __forceinline__ float sigm(float v){ return 1.0f/(1.0f + __expf(-v)); }

// ---- packed f32x2 helpers ----
typedef unsigned long long u64;
__device__ __forceinline__ u64 pk2(float lo, float hi){
  u64 r; asm("mov.b64 %0, {%1,%2};" : "=l"(r) : "f"(lo), "f"(hi)); return r;
}
__device__ __forceinline__ void fma2(u64 &d, u64 a, u64 b){
  asm("fma.rn.f32x2 %0, %1, %2, %0;" : "+l"(d) : "l"(a), "l"(b));
}
__device__ __forceinline__ float2 upk2(u64 v){
  float2 f; asm("mov.b64 {%0,%1}, %2;" : "=f"(f.x), "=f"(f.y) : "l"(v)); return f;
}

// Shared CBAM response path: MUST be identical in k_thr and k_final.
__device__ __forceinline__ void group_resp(const float* xv, const float* cw8,
                                           const float* sw8, float sbg, float* resp)
{
  float xc[8]; float dot = sbg;
  #pragma unroll
  for (int c=0;c<8;c++){ xc[c] = xv[c]*cw8[c]; dot = fmaf(xc[c], sw8[c], dot); }
  float sp = sigm(dot);
  #pragma unroll
  for (int c=0;c<8;c++) resp[c] = sigm(xc[c]*sp);
}

// ------------------------------- k_prep -------------------------------
__global__ void k_prep(const float* __restrict__ pw, const float* __restrict__ prew,
                       const float* __restrict__ qw, const float* __restrict__ g1,
                       const float* __restrict__ postw, const float* __restrict__ poutw)
{
  int t = blockIdx.x*256 + threadIdx.x;
  int nt = gridDim.x*256;
  for (int i=t; i<128*128; i+=nt){ int o=i>>7, c=i&127; g_projT[c*128+o]=pw[i]; g_poutT[c*128+o]=poutw[i]; }
  for (int i=t; i<64*64;  i+=nt){ int o=i>>6, c=i&63;  g_preT[c*64+o]=prew[i]; g_postT[c*64+o]=postw[i]; }
  for (int i=t; i<192*64; i+=nt){ int o=i/64, c=i%64;  g_qkvT[(o>>6)*4096 + c*64 + (o&63)] = qw[i]; }
  for (int i=t; i<32*64;  i+=nt){ int o=i>>6, c=i&63;  g_g1T[c*32+o]=g1[i]; }
  if (t < 256){ g_pooled[t]=0.0; g_qss[t]=0.0; g_kss[t]=0.0; }
  for (int i=t; i<2048; i+=nt) g_gram[i]=0.0;
  if (t < 32) g_resp_sum[t]=0.0;
  if (t == 0) g_gate_sum=0.0;
}

// ------------------------------- k_front: proj + pre + gate + qkv -------------------------------
#define FR_XS   8192
#define FR_SP   (8192 + 128*132)   // 25088
#define FR_TOT  (25088 + 512)      // 25600 floats = 100 KB -> 2 CTA/SM

__global__ void __launch_bounds__(256,2) k_front(
    const float* __restrict__ x, const float* __restrict__ pre_b,
    const float* __restrict__ gate_b1, const float* __restrict__ gate_w2,
    const float* __restrict__ gate_b2)
{
  extern __shared__ float sm[];
  float* ws    = sm;
  float* xs    = sm + FR_XS;
  float* spool = sm + FR_SP;
  int tid = threadIdx.x;
  int b   = blockIdx.x >> 9;
  int pb  = (blockIdx.x & 511) << 7;
  int oi  = tid & 31;
  int pg  = tid >> 5;       // 0..7 (warp-constant)
  int px0 = pg << 4;

  // load x tile
  const float* xb = x + (size_t)b*128*HW + pb;
  for (int i=tid; i<128*32; i+=256){
    int ch=i>>5, q=i&31;
    ((float4*)(xs + ch*132))[q] = __ldg((const float4*)(xb + (size_t)ch*HW) + q);
  }

  // ---- input_proj, 2 K-chunks ----
  u64 acc[4][8];
  #pragma unroll
  for (int i=0;i<4;i++){
    #pragma unroll
    for (int j=0;j<8;j++) acc[i][j]=0ull;
  }
  #pragma unroll
  for (int c=0;c<2;c++){
    __syncthreads();
    for (int i=tid; i<64*32; i+=256) ((float4*)ws)[i] = ((const float4*)(g_projT + c*8192))[i];
    __syncthreads();
    for (int kk=0; kk<64; kk++){
      const ulonglong2* xr = (const ulonglong2*)(xs + (c*64+kk)*132 + px0);
      ulonglong2 x01 = xr[0], x23 = xr[1], x45 = xr[2], x67 = xr[3];
      u64 xv[8] = {x01.x,x01.y,x23.x,x23.y,x45.x,x45.y,x67.x,x67.y};
      const float* wrow = ws + kk*128;
      #pragma unroll
      for (int i=0;i<4;i++){
        float w = wrow[oi + 32*i];
        u64 wp = pk2(w,w);
        #pragma unroll
        for (int j=0;j<8;j++) fma2(acc[i][j], wp, xv[j]);
      }
    }
  }
  __syncthreads();   // all xs reads done
  #pragma unroll
  for (int i=0;i<4;i++){
    ulonglong2* dst = (ulonglong2*)(xs + (oi+32*i)*132 + px0);
    #pragma unroll
    for (int m=0;m<4;m++){ ulonglong2 v; v.x=acc[i][2*m]; v.y=acc[i][2*m+1]; dst[m]=v; }
  }
  __syncthreads();

  // ---- store lb; load preT ----
  {
    float* lbp = g_lb + (size_t)b*64*HW + pb;
    for (int i=tid; i<64*32; i+=256){
      int ch=i>>5, q=i&31;
      *((float4*)(lbp + (size_t)ch*HW) + q) = ((const float4*)(xs + ch*132))[q];
    }
    for (int i=tid; i<64*16; i+=256) ((float4*)ws)[i] = ((const float4*)g_preT)[i];
  }
  __syncthreads();

  // ---- lgce pre conv (reads rows 0..63, writes rows 0..63 after reads) ----
  {
    u64 a2[2][8];
    #pragma unroll
    for (int i=0;i<2;i++){
      #pragma unroll
      for (int j=0;j<8;j++) a2[i][j]=0ull;
    }
    for (int k=0; k<64; k++){
      const ulonglong2* xr = (const ulonglong2*)(xs + k*132 + px0);
      ulonglong2 x01 = xr[0], x23 = xr[1], x45 = xr[2], x67 = xr[3];
      u64 xv[8] = {x01.x,x01.y,x23.x,x23.y,x45.x,x45.y,x67.x,x67.y};
      const float* wrow = ws + k*64;
      #pragma unroll
      for (int i=0;i<2;i++){
        float w = wrow[oi + 32*i];
        u64 wp = pk2(w,w);
        #pragma unroll
        for (int j=0;j<8;j++) fma2(a2[i][j], wp, xv[j]);
      }
    }
    __syncthreads();   // all reads of rows 0..63 done
    #pragma unroll
    for (int i=0;i<2;i++){
      int o = oi + 32*i;
      float bb = __ldg(pre_b + o);
      float psum = 0.f;
      float* dst = xs + o*132 + px0;
      #pragma unroll
      for (int j=0;j<8;j++){
        float2 v = upk2(a2[i][j]);
        v.x += bb; v.y += bb;
        psum += v.x + v.y;
        *((float2*)(dst + 2*j)) = v;
      }
      spool[o*8 + pg] = psum;
    }
  }
  __syncthreads();

  // ---- store xpre + pooled; load g1T ----
  {
    float* xpp = g_xpre + (size_t)b*64*HW + pb;
    for (int i=tid; i<64*32; i+=256){
      int ch=i>>5, q=i&31;
      *((float4*)(xpp + (size_t)ch*HW) + q) = ((const float4*)(xs + ch*132))[q];
    }
    if (tid < 64){
      float s = 0.f;
      #pragma unroll
      for (int t2=0;t2<8;t2++) s += spool[tid*8 + t2];
      atomicAdd(&g_pooled[b*64 + tid], (double)s);
    }
    for (int i=tid; i<64*8; i+=256) ((float4*)ws)[i] = ((const float4*)g_g1T)[i];
  }
  __syncthreads();

  // ---- gate hidden ----
  {
    float* hid = ws + 2048;   // 128*33
    int px = tid & 127;
    int o0 = (tid >> 7) << 4;
    u64 ga[8];
    #pragma unroll
    for (int i=0;i<8;i++) ga[i]=0ull;
    #pragma unroll 4
    for (int k=0;k<64;k++){
      float xv = xs[(64+k)*132 + px];
      u64 xp = pk2(xv,xv);
      const float4* wr = (const float4*)(ws + k*32 + o0);
      float4 w0 = wr[0], w1 = wr[1], w2v = wr[2], w3 = wr[3];
      fma2(ga[0], pk2(w0.x,w0.y), xp);
      fma2(ga[1], pk2(w0.z,w0.w), xp);
      fma2(ga[2], pk2(w1.x,w1.y), xp);
      fma2(ga[3], pk2(w1.z,w1.w), xp);
      fma2(ga[4], pk2(w2v.x,w2v.y), xp);
      fma2(ga[5], pk2(w2v.z,w2v.w), xp);
      fma2(ga[6], pk2(w3.x,w3.y), xp);
      fma2(ga[7], pk2(w3.z,w3.w), xp);
    }
    #pragma unroll
    for (int i=0;i<8;i++){
      float2 v = upk2(ga[i]);
      hid[px*33 + o0 + 2*i]     = fmaxf(v.x + __ldg(gate_b1 + o0 + 2*i), 0.f);
      hid[px*33 + o0 + 2*i + 1] = fmaxf(v.y + __ldg(gate_b1 + o0 + 2*i + 1), 0.f);
    }
  }
  __syncthreads();
  if (tid < 128){
    const float* hid = ws + 2048;
    float g = __ldg(gate_b2);
    #pragma unroll
    for (int h=0;h<32;h++) g = fmaf(hid[tid*33+h], __ldg(gate_w2+h), g);
    g = sigm(g);
    #pragma unroll
    for (int off=16; off; off>>=1) g += __shfl_down_sync(0xffffffffu, g, off);
    if ((tid&31)==0) atomicAdd(&g_gate_sum, (double)g);
  }

  // ---- qkv: 3 out-chunks of 64, staging in rows 0..63 ----
  float* qp = g_qkv + (size_t)b*192*HW + pb;
  for (int cc=0; cc<3; cc++){
    __syncthreads();   // hid reads / prior stage-store reads done
    for (int i=tid; i<64*16; i+=256) ((float4*)ws)[i] = ((const float4*)(g_qkvT + cc*4096))[i];
    __syncthreads();
    u64 a2[2][8];
    #pragma unroll
    for (int i=0;i<2;i++){
      #pragma unroll
      for (int j=0;j<8;j++) a2[i][j]=0ull;
    }
    for (int k=0; k<64; k++){
      const ulonglong2* xr = (const ulonglong2*)(xs + (64+k)*132 + px0);
      ulonglong2 x01 = xr[0], x23 = xr[1], x45 = xr[2], x67 = xr[3];
      u64 xv[8] = {x01.x,x01.y,x23.x,x23.y,x45.x,x45.y,x67.x,x67.y};
      const float* wrow = ws + k*64;
      #pragma unroll
      for (int i=0;i<2;i++){
        float w = wrow[oi + 32*i];
        u64 wp = pk2(w,w);
        #pragma unroll
        for (int j=0;j<8;j++) fma2(a2[i][j], wp, xv[j]);
      }
    }
    // stage into rows 0..63 (disjoint from compute reads; prior readers synced)
    #pragma unroll
    for (int i=0;i<2;i++){
      ulonglong2* dst = (ulonglong2*)(xs + (oi+32*i)*132 + px0);
      #pragma unroll
      for (int m=0;m<4;m++){ ulonglong2 v; v.x=a2[i][2*m]; v.y=a2[i][2*m+1]; dst[m]=v; }
    }
    __syncthreads();
    for (int t=tid; t<64*32; t+=256){
      int ch=t>>5, q=t&31;
      *((float4*)(qp + (size_t)(cc*64+ch)*HW) + q) = ((const float4*)(xs + ch*132))[q];
    }
  }
}

// ------------------------------- k_dw: depthwise 3x3 SAME, V ONLY -------------------------------
__global__ void __launch_bounds__(256) k_dw(const float* __restrict__ dww)
{
  int bid = blockIdx.x;                 // 256 * 64
  int bcv = bid >> 6;                   // b*64 + cv
  int bb  = bcv >> 6, cv = bcv & 63;
  int ch  = 128 + cv;
  int y   = ((bid & 63) << 2) + (threadIdx.x >> 6);
  int xq  = (threadIdx.x & 63) << 2;
  float w[9];
  #pragma unroll
  for (int i=0;i<9;i++) w[i] = __ldg(dww + ch*9 + i);
  const float* img = g_qkv + (size_t)(bb*192 + ch)*HW;
  float v[3][6];
  #pragma unroll
  for (int r=0;r<3;r++){
    int yy = y - 1 + r;
    if ((unsigned)yy < 256u){
      float4 c4 = __ldg((const float4*)(img + yy*IMW + xq));
      v[r][1]=c4.x; v[r][2]=c4.y; v[r][3]=c4.z; v[r][4]=c4.w;
      v[r][0] = (xq > 0)   ? __ldg(img + yy*IMW + xq - 1) : 0.f;
      v[r][5] = (xq < 252) ? __ldg(img + yy*IMW + xq + 4) : 0.f;
    } else {
      #pragma unroll
      for (int j=0;j<6;j++) v[r][j]=0.f;
    }
  }
  float o[4];
  #pragma unroll
  for (int j=0;j<4;j++){
    float s=0.f;
    #pragma unroll
    for (int r=0;r<3;r++){
      s = fmaf(v[r][j],   w[r*3+0], s);
      s = fmaf(v[r][j+1], w[r*3+1], s);
      s = fmaf(v[r][j+2], w[r*3+2], s);
    }
    o[j]=s;
  }
  float4 ov = {o[0],o[1],o[2],o[3]};
  *((float4*)(g_vd + (size_t)(bb*64 + cv)*HW + y*IMW + xq)) = ov;
}

// ------------------------------- k_small -------------------------------
__global__ void k_small(const float* __restrict__ w1, const float* __restrict__ b1,
                        const float* __restrict__ w2, const float* __restrict__ b2)
{
  int t = threadIdx.x;
  if (t < 32){
    int b = t >> 3, g = t & 7;
    float pooled[8];
    #pragma unroll
    for (int c=0;c<8;c++) pooled[c] = (float)(g_pooled[b*64 + g*8 + c] * (1.0/65536.0));
    float h0 = b1[g*2+0], h1 = b1[g*2+1];
    #pragma unroll
    for (int c=0;c<8;c++){
      h0 = fmaf(pooled[c], w1[g*16 + 0*8 + c], h0);
      h1 = fmaf(pooled[c], w1[g*16 + 1*8 + c], h1);
    }
    h0 = fmaxf(h0, 0.f); h1 = fmaxf(h1, 0.f);
    #pragma unroll
    for (int c=0;c<8;c++){
      float v = b2[g*8+c];
      v = fmaf(h0, w2[g*16 + c*2 + 0], v);
      v = fmaf(h1, w2[g*16 + c*2 + 1], v);
      g_cw[b*64 + g*8 + c] = sigm(v);
    }
    if (t == 0){
      float mean = (float)(g_gate_sum * (1.0/262144.0));
      g_kdyn = fminf(fmaxf(floorf(8.f*mean), 1.f), 8.f);
    }
  }
}

// ------------------------------- k_thr: 1 px/thread, 1024 blocks --------------
__global__ void __launch_bounds__(256) k_thr(const float* __restrict__ sw, const float* __restrict__ sb)
{
  __shared__ float cw_s[64], sw_s[64], sb_s[8];
  __shared__ float ssum[8];
  int tid = threadIdx.x;
  int b = blockIdx.x >> 8;
  int p = ((blockIdx.x & 255) << 8) + tid;
  if (tid < 64){ cw_s[tid] = g_cw[b*64 + tid]; sw_s[tid] = __ldg(sw + tid); }
  if (tid < 8){ sb_s[tid] = __ldg(sb + tid); ssum[tid] = 0.f; }
  __syncthreads();
  const float* xp = g_xpre + (size_t)b*64*HW + p;
  #pragma unroll
  for (int g=0; g<8; g++){
    float xv[8], resp[8];
    #pragma unroll
    for (int c=0;c<8;c++) xv[c] = __ldg(xp + (size_t)(g*8+c)*HW);
    group_resp(xv, cw_s + g*8, sw_s + g*8, sb_s[g], resp);
    float s = 0.f;
    #pragma unroll
    for (int c=0;c<8;c++) s += resp[c];
    #pragma unroll
    for (int off=16; off; off>>=1) s += __shfl_down_sync(0xffffffffu, s, off);
    if ((tid&31)==0) atomicAdd(&ssum[g], s);
  }
  __syncthreads();
  if (tid < 8) atomicAdd(&g_resp_sum[b*8 + tid], (double)ssum[tid]);
}

// ------------------------------- k_gram: fused dwconv(q,k) + Gram, k-split -------------------------------
// grid = 4b * 8h * 32 strips * 2 k-halves = 2048 blocks, 256 threads = 256 columns.
// Block computes gr[8 q-ch][4 k-ch]; qs added only by kh==0 (else double-counted);
// ks[4] halves are disjoint. smem: sbuf 12ch x 3rows x 264 | wdw 108 | wred 352
#define GM_WDW  (12*792)            // 9504
#define GM_WRED (9504 + 108)        // 9612
#define GM_TOT  (9612 + 352)        // 9964 floats = 39.9 KB -> 3 CTA/SM

__global__ void __launch_bounds__(256,3) k_gram(const float* __restrict__ dww)
{
  extern __shared__ float sm[];
  float* sbuf = sm;
  float* wdw  = sm + GM_WDW;
  float* wred = sm + GM_WRED;
  int tid = threadIdx.x;
  int bh    = blockIdx.x >> 6;
  int strip = (blockIdx.x >> 1) & 31;
  int kh    = blockIdx.x & 1;
  int b = bh >> 3, h = bh & 7;
  int r0 = strip << 3;

  if (tid < 108){
    int c = tid/9, j = tid%9;
    int ch = (c<8) ? (h*8+c) : (64 + h*8 + kh*4 + (c-8));
    wdw[tid] = __ldg(dww + ch*9 + j);
  }

  // row loader: global row ry -> slot (ry mod 3); zero-pads edge cells. 12 channels.
  auto load_row = [&](int ry){
    int s = ((ry % 3) + 3) % 3;
    for (int i=tid; i<768; i+=256){
      int c = i>>6, q = i&63;
      float4 v = {0.f,0.f,0.f,0.f};
      if ((unsigned)ry < 256u){
        int ch = (c<8) ? (h*8+c) : (64 + h*8 + kh*4 + (c-8));
        v = __ldg((const float4*)(g_qkv + (size_t)(b*192+ch)*HW + ry*IMW) + q);
      }
      *((float4*)(sbuf + c*792 + s*264 + 4 + 4*q)) = v;
    }
    if (tid < 24){
      int c = tid>>1, side = tid&1;
      sbuf[c*792 + s*264 + (side ? 260 : 3)] = 0.f;
    }
  };

  float gr[8][4], qs[8], ks[4];
  #pragma unroll
  for (int c=0;c<8;c++){
    qs[c]=0.f;
    #pragma unroll
    for (int d=0;d<4;d++) gr[c][d]=0.f;
  }
  #pragma unroll
  for (int d=0;d<4;d++) ks[d]=0.f;

  load_row(r0-1);
  load_row(r0);
  int col = tid;
  for (int y=r0; y<r0+8; y++){
    load_row(y+1);
    __syncthreads();
    int s0 = ((y-1)%3 + 3)%3, s1 = y%3, s2 = (y+1)%3;
    int srow[3] = {s0, s1, s2};
    float q[8], k[4];
    #pragma unroll
    for (int c=0;c<8;c++){
      float aq = 0.f;
      #pragma unroll
      for (int r=0;r<3;r++){
        const float* pq = sbuf + c*792 + srow[r]*264 + 3 + col;
        const float* wq = wdw + c*9 + r*3;
        aq = fmaf(pq[0], wq[0], aq); aq = fmaf(pq[1], wq[1], aq); aq = fmaf(pq[2], wq[2], aq);
      }
      q[c]=aq;
    }
    #pragma unroll
    for (int d=0;d<4;d++){
      float ak = 0.f;
      #pragma unroll
      for (int r=0;r<3;r++){
        const float* pk = sbuf + (8+d)*792 + srow[r]*264 + 3 + col;
        const float* wk = wdw + 72 + d*9 + r*3;
        ak = fmaf(pk[0], wk[0], ak); ak = fmaf(pk[1], wk[1], ak); ak = fmaf(pk[2], wk[2], ak);
      }
      k[d]=ak;
      ks[d]=fmaf(ak,ak,ks[d]);
    }
    #pragma unroll
    for (int c=0;c<8;c++){
      qs[c]=fmaf(q[c],q[c],qs[c]);
      #pragma unroll
      for (int d=0;d<4;d++) gr[c][d]=fmaf(q[c],k[d],gr[c][d]);
    }
    __syncthreads();   // reads of slot s0 done before next load overwrites it
  }

  // warp shuffle reduce -> smem -> global fp64 atomics
  int lane = tid & 31, wd = tid >> 5;
  #pragma unroll
  for (int c=0;c<8;c++){
    #pragma unroll
    for (int d=0;d<4;d++){
      float v = gr[c][d];
      #pragma unroll
      for (int o=16;o;o>>=1) v += __shfl_down_sync(0xffffffffu, v, o);
      if (lane==0) wred[wd*44 + c*4 + d] = v;
    }
    float v = qs[c];
    #pragma unroll
    for (int o=16;o;o>>=1) v += __shfl_down_sync(0xffffffffu, v, o);
    if (lane==0) wred[wd*44 + 32 + c] = v;
  }
  #pragma unroll
  for (int d=0;d<4;d++){
    float u = ks[d];
    #pragma unroll
    for (int o=16;o;o>>=1) u += __shfl_down_sync(0xffffffffu, u, o);
    if (lane==0) wred[wd*44 + 40 + d] = u;
  }
  __syncthreads();
  if (tid < 44){
    float s = 0.f;
    #pragma unroll
    for (int ww=0; ww<8; ww++) s += wred[ww*44 + tid];
    if (tid < 32){
      int c = tid >> 2, d = tid & 3;
      atomicAdd(&g_gram[(b*8+h)*64 + c*8 + kh*4 + d], (double)s);
    } else if (tid < 40){
      if (kh == 0) atomicAdd(&g_qss[b*64 + h*8 + (tid-32)], (double)s);
    } else {
      atomicAdd(&g_kss[b*64 + h*8 + kh*4 + (tid-40)], (double)s);
    }
  }
}

// ------------------------------- k_attn -------------------------------
__global__ void k_attn(const float* __restrict__ temp, const float* __restrict__ scales)
{
  int t = threadIdx.x;
  if (t >= 32) return;
  int b = t >> 3, h = t & 7;
  float scl = scales[0] + scales[1] + scales[2] + scales[3];
  float T   = temp[h];
  float kd  = g_kdyn;
  float nq[8], nk[8];
  #pragma unroll
  for (int c=0;c<8;c++){
    nq[c] = fmaxf(sqrtf((float)g_qss[b*64 + h*8 + c]), 1e-12f);
    nk[c] = fmaxf(sqrtf((float)g_kss[b*64 + h*8 + c]), 1e-12f);
  }
  float a[8][8];
  #pragma unroll
  for (int c=0;c<8;c++){
    #pragma unroll
    for (int d=0;d<8;d++)
      a[c][d] = ((float)g_gram[(b*8+h)*64 + c*8 + d]) / (nq[c]*nk[d]) * T;
  }
  #pragma unroll
  for (int c=0;c<8;c++){
    bool keep[8];
    #pragma unroll
    for (int d=0;d<8;d++){
      int r = 0;
      #pragma unroll
      for (int e=0;e<8;e++)
        r += (a[c][e] > a[c][d]) || (a[c][e] == a[c][d] && e < d);
      keep[d] = ((float)r < kd);
    }
    float m = -1e30f;
    #pragma unroll
    for (int d=0;d<8;d++) if (keep[d]) m = fmaxf(m, a[c][d]);
    float pr[8]; float sum = 0.f;
    #pragma unroll
    for (int d=0;d<8;d++){ pr[d] = keep[d] ? __expf(a[c][d]-m) : 0.f; sum += pr[d]; }
    float inv = scl / sum;
    #pragma unroll
    for (int d=0;d<8;d++) g_attnw[((b*8+h)*8 + c)*8 + d] = pr[d]*inv;
  }
}

// ------------------------------- k_final: 128-px tiles, 512 threads -------------------------------
#define FN_XS  16384
#define FN_VB  (16384 + 64*132)          // 24832
#define FN_WS  (24832 + 64*132)          // 33280
#define FN_CW  (33280 + 512)             // 33792
#define FN_THR (33792 + 64)              // 33856
#define FN_TOT (33856 + 8)               // 33864 floats = 135.5 KB -> 1 CTA (16 warps)

__global__ void __launch_bounds__(512,1) k_final(
    const float* __restrict__ sw, const float* __restrict__ sb,
    const float* __restrict__ post_b, float* __restrict__ out)
{
  extern __shared__ float sm[];
  float* wb    = sm;
  float* xs    = sm + FN_XS;
  float* vb    = sm + FN_VB;
  float* W_s   = sm + FN_WS;
  float* cw_s  = sm + FN_CW;
  float* thr_s = sm + FN_THR;

  int tid = threadIdx.x;
  int b   = blockIdx.x >> 9;
  int pb  = (blockIdx.x & 511) << 7;
  int oi  = tid & 63;
  int qg  = tid >> 6;        // 0..7 (warp-pair constant)
  int px0 = qg << 4;

  for (int i=tid; i<1024; i+=512) ((float4*)wb)[i] = ((const float4*)g_postT)[i];
  for (int i=tid; i<512;  i+=512) W_s[i] = g_attnw[b*512 + i];
  if (tid < 64) cw_s[tid] = g_cw[b*64 + tid];
  if (tid < 8)  thr_s[tid] = (float)(g_resp_sum[b*8 + tid] * (1.0/524288.0));
  {
    const float* xp  = g_xpre + (size_t)b*64*HW + pb;
    const float* lbp = g_lb   + (size_t)b*64*HW + pb;
    for (int i=tid; i<64*32; i+=512){
      int ch=i>>5, q=i&31;
      ((float4*)(xs + ch*132))[q] = __ldg((const float4*)(xp  + (size_t)ch*HW) + q);
      ((float4*)(vb + ch*132))[q] = __ldg((const float4*)(lbp + (size_t)ch*HW) + q);
    }
  }
  __syncthreads();

  // mask in place (same group_resp as k_thr): 128 px x 8 groups / 512 threads
  {
    int p  = tid & 127;
    int g0 = (tid >> 7) << 1;
    #pragma unroll
    for (int gi=0; gi<2; gi++){
      int g = g0 + gi;
      float xv[8], resp[8], sw8[8];
      #pragma unroll
      for (int c=0;c<8;c++){ xv[c] = xs[(g*8+c)*132 + p]; sw8[c] = __ldg(sw + g*8 + c); }
      group_resp(xv, cw_s + g*8, sw8, __ldg(sb + g), resp);
      float thr = thr_s[g];
      #pragma unroll
      for (int c=0;c<8;c++){
        float m = resp[c] > thr ? 1.f : resp[c];
        xs[(g*8+c)*132 + p] = xv[c]*m;
      }
    }
  }
  __syncthreads();

  // post conv: out oi x 16 px, K=64; + bias + residual (vb = lb)
  float pres[16];
  {
    u64 pa[8];
    #pragma unroll
    for (int j=0;j<8;j++) pa[j]=0ull;
    for (int k=0; k<64; k++){
      const ulonglong2* xr = (const ulonglong2*)(xs + k*132 + px0);
      ulonglong2 x01 = xr[0], x23 = xr[1], x45 = xr[2], x67 = xr[3];
      u64 xv[8] = {x01.x,x01.y,x23.x,x23.y,x45.x,x45.y,x67.x,x67.y};
      float w = wb[k*64 + oi];
      u64 wp = pk2(w,w);
      #pragma unroll
      for (int j=0;j<8;j++) fma2(pa[j], wp, xv[j]);
    }
    float bb = __ldg(post_b + oi);
    const float* rr = vb + oi*132 + px0;
    #pragma unroll
    for (int j=0;j<8;j++){
      float2 v = upk2(pa[j]);
      pres[2*j]   = v.x + bb + rr[2*j];
      pres[2*j+1] = v.y + bb + rr[2*j+1];
    }
  }
  __syncthreads();
  {
    float* dst = xs + oi*132 + px0;
    #pragma unroll
    for (int j=0;j<8;j++) *((float2*)(dst + 2*j)) = make_float2(pres[2*j], pres[2*j+1]);
    const float* vp = g_vd + (size_t)b*64*HW + pb;
    for (int i=tid; i<64*32; i+=512){
      int ch=i>>5, q=i&31;
      ((float4*)(vb + ch*132))[q] = __ldg((const float4*)(vp + (size_t)ch*HW) + q);
    }
  }
  __syncthreads();

  // attn mix: out oi (head oi>>3), 16 px
  {
    int h = oi >> 3;
    u64 aa[8];
    #pragma unroll
    for (int j=0;j<8;j++) aa[j]=0ull;
    #pragma unroll
    for (int d=0;d<8;d++){
      float w = W_s[oi*8 + d];
      u64 wp = pk2(w,w);
      const ulonglong2* xr = (const ulonglong2*)(vb + (h*8+d)*132 + px0);
      ulonglong2 x01 = xr[0], x23 = xr[1], x45 = xr[2], x67 = xr[3];
      fma2(aa[0], wp, x01.x); fma2(aa[1], wp, x01.y);
      fma2(aa[2], wp, x23.x); fma2(aa[3], wp, x23.y);
      fma2(aa[4], wp, x45.x); fma2(aa[5], wp, x45.y);
      fma2(aa[6], wp, x67.x); fma2(aa[7], wp, x67.y);
    }
    __syncthreads();   // all vb reads done
    ulonglong2* dst = (ulonglong2*)(vb + oi*132 + px0);
    #pragma unroll
    for (int m=0;m<4;m++){ ulonglong2 v; v.x=aa[2*m]; v.y=aa[2*m+1]; dst[m]=v; }
    for (int i=tid; i<4096; i+=512) ((float4*)wb)[i] = ((const float4*)g_poutT)[i];
  }
  __syncthreads();

  // proj_out: outs (oi, oi+64) x 16 px, K=128 (k<64 -> vb=attn, k>=64 -> xs=post)
  {
    u64 po[2][8];
    #pragma unroll
    for (int i=0;i<2;i++){
      #pragma unroll
      for (int j=0;j<8;j++) po[i][j]=0ull;
    }
    for (int k=0; k<64; k++){
      const ulonglong2* xr = (const ulonglong2*)(vb + k*132 + px0);
      ulonglong2 x01 = xr[0], x23 = xr[1], x45 = xr[2], x67 = xr[3];
      u64 xv[8] = {x01.x,x01.y,x23.x,x23.y,x45.x,x45.y,x67.x,x67.y};
      const float* wrow = wb + k*128;
      #pragma unroll
      for (int i=0;i<2;i++){
        float w = wrow[oi + 64*i];
        u64 wp = pk2(w,w);
        #pragma unroll
        for (int j=0;j<8;j++) fma2(po[i][j], wp, xv[j]);
      }
    }
    for (int k=0; k<64; k++){
      const ulonglong2* xr = (const ulonglong2*)(xs + k*132 + px0);
      ulonglong2 x01 = xr[0], x23 = xr[1], x45 = xr[2], x67 = xr[3];
      u64 xv[8] = {x01.x,x01.y,x23.x,x23.y,x45.x,x45.y,x67.x,x67.y};
      const float* wrow = wb + (64+k)*128;
      #pragma unroll
      for (int i=0;i<2;i++){
        float w = wrow[oi + 64*i];
        u64 wp = pk2(w,w);
        #pragma unroll
        for (int j=0;j<8;j++) fma2(po[i][j], wp, xv[j]);
      }
    }
    __syncthreads();   // all vb/xs reads done
    ulonglong2* d0 = (ulonglong2*)(vb + oi*132 + px0);
    ulonglong2* d1 = (ulonglong2*)(xs + oi*132 + px0);
    #pragma unroll
    for (int m=0;m<4;m++){
      ulonglong2 v0; v0.x=po[0][2*m]; v0.y=po[0][2*m+1]; d0[m]=v0;
      ulonglong2 v1; v1.x=po[1][2*m]; v1.y=po[1][2*m+1]; d1[m]=v1;
    }
  }
  __syncthreads();
  {
    float* op = out + (size_t)b*128*HW + pb;
    for (int i=tid; i<64*32; i+=512){
      int ch=i>>5, q=i&31;
      *((float4*)(op + (size_t)ch*HW) + q)      = ((const float4*)(vb + ch*132))[q];
      *((float4*)(op + (size_t)(64+ch)*HW) + q) = ((const float4*)(xs + ch*132))[q];
    }
  }
}

// ------------------------------- launch -------------------------------
extern "C" void kernel_launch(void* const* d_in, const int* in_sizes, int n_in,
                              void* d_out, int out_size)
{
  const float* x      = (const float*)d_in[0];
  const float* projw  = (const float*)d_in[1];
  const float* prew   = (const float*)d_in[2];
  const float* preb   = (const float*)d_in[3];
  const float* w1     = (const float*)d_in[4];
  const float* b1     = (const float*)d_in[5];
  const float* w2     = (const float*)d_in[6];
  const float* b2     = (const float*)d_in[7];
  const float* sw     = (const float*)d_in[8];
  const float* sb     = (const float*)d_in[9];
  const float* postw  = (const float*)d_in[10];
  const float* postb  = (const float*)d_in[11];
  const float* qkvw   = (const float*)d_in[12];
  const float* dww    = (const float*)d_in[13];
  const float* gw1    = (const float*)d_in[14];
  const float* gb1    = (const float*)d_in[15];
  const float* gw2    = (const float*)d_in[16];
  const float* gb2    = (const float*)d_in[17];
  const float* temp   = (const float*)d_in[18];
  const float* scales = (const float*)d_in[19];
  const float* poutw  = (const float*)d_in[20];
  float* out = (float*)d_out;

  cudaFuncSetAttribute(k_front, cudaFuncAttributeMaxDynamicSharedMemorySize, FR_TOT*4);
  cudaFuncSetAttribute(k_gram,  cudaFuncAttributeMaxDynamicSharedMemorySize, GM_TOT*4);
  cudaFuncSetAttribute(k_final, cudaFuncAttributeMaxDynamicSharedMemorySize, FN_TOT*4);

  // Fork/join across streams (capture-safe event pattern). Stream/event
  // create+destroy are host-side only; the captured graph keeps just the edges.
  cudaStream_t s1, s2;
  cudaStreamCreateWithFlags(&s1, cudaStreamNonBlocking);
  cudaStreamCreateWithFlags(&s2, cudaStreamNonBlocking);
  cudaEvent_t eF, e1, e2;
  cudaEventCreateWithFlags(&eF, cudaEventDisableTiming);
  cudaEventCreateWithFlags(&e1, cudaEventDisableTiming);
  cudaEventCreateWithFlags(&e2, cudaEventDisableTiming);

  k_prep <<<64, 256>>>(projw, prew, qkvw, gw1, postw, poutw);
  k_front<<<2048, 256, FR_TOT*4>>>(x, preb, gb1, gw2, gb2);
  cudaEventRecord(eF, 0);

  // s1: depthwise v-conv (needs g_qkv only)
  cudaStreamWaitEvent(s1, eF, 0);
  k_dw<<<256*64, 256, 0, s1>>>(dww);
  cudaEventRecord(e1, s1);

  // s2: fused q/k dwconv + gram, k-split (needs g_qkv only)
  cudaStreamWaitEvent(s2, eF, 0);
  k_gram<<<2048, 256, GM_TOT*4, s2>>>(dww);
  cudaEventRecord(e2, s2);

  // main: cw/kdyn then resp-threshold (needs g_pooled/gate + g_xpre + cw)
  k_small<<<1, 32>>>(w1, b1, w2, b2);
  k_thr  <<<1024, 256>>>(sw, sb);

  // join: attn needs gram(+kdyn); final needs everything
  cudaStreamWaitEvent(0, e2, 0);
  k_attn <<<1, 32>>>(temp, scales);
  cudaStreamWaitEvent(0, e1, 0);
  k_final<<<2048, 512, FN_TOT*4>>>(sw, sb, postb, out);

  cudaEventDestroy(eF); cudaEventDestroy(e1); cudaEventDestroy(e2);
  cudaStreamDestroy(s1); cudaStreamDestroy(s2);
}

// round 14
// speedup vs baseline: 1.0988x; 1.0988x over previous
#include <cuda_runtime.h>

#define HW 65536
#define IMW 256

// ------------------------- device scratch (no allocations) -------------------------
static __device__ __align__(16) float g_projT[128*128];
static __device__ __align__(16) float g_preT [64*64];
static __device__ __align__(16) float g_qkvT [3*64*64];   // chunk-major: [cc][k][64]
static __device__ __align__(16) float g_g1T  [64*32];
static __device__ __align__(16) float g_postT[64*64];
static __device__ __align__(16) float g_poutT[128*128];

static __device__ __align__(16) float g_lb  [(size_t)4*64*HW];   // local branch residual
static __device__ __align__(16) float g_xpre[(size_t)4*64*HW];   // lgce pre-conv output
static __device__ __align__(16) float g_qkv [(size_t)4*192*HW];  // qkv (pre-dwconv)
static __device__ __align__(16) float g_vd  [(size_t)4*64*HW];   // dwconv'd v

static __device__ double g_pooled[4*64];
static __device__ double g_gate_sum;
static __device__ double g_resp_sum[4*8];
static __device__ double g_gram[4*8*64];
static __device__ double g_qss[4*64];
static __device__ double g_kss[4*64];
static __device__ float  g_cw[4*64];
static __device__ float  g_kdyn;
static __device__ float  g_attnw[4*8*64];

__device__ __forceinline__ float sigm(float v){ return 1.0f/(1.0f + __expf(-v)); }

// ---- packed f32x2 helpers ----
typedef unsigned long long u64;
__device__ __forceinline__ u64 pk2(float lo, float hi){
  u64 r; asm("mov.b64 %0, {%1,%2};" : "=l"(r) : "f"(lo), "f"(hi)); return r;
}
__device__ __forceinline__ void fma2(u64 &d, u64 a, u64 b){
  asm("fma.rn.f32x2 %0, %1, %2, %0;" : "+l"(d) : "l"(a), "l"(b));
}
__device__ __forceinline__ float2 upk2(u64 v){
  float2 f; asm("mov.b64 {%0,%1}, %2;" : "=f"(f.x), "=f"(f.y) : "l"(v)); return f;
}

// Shared CBAM response path: MUST be identical in k_thr and k_final.
__device__ __forceinline__ void group_resp(const float* xv, const float* cw8,
                                           const float* sw8, float sbg, float* resp)
{
  float xc[8]; float dot = sbg;
  #pragma unroll
  for (int c=0;c<8;c++){ xc[c] = xv[c]*cw8[c]; dot = fmaf(xc[c], sw8[c], dot); }
  float sp = sigm(dot);
  #pragma unroll
  for (int c=0;c<8;c++) resp[c] = sigm(xc[c]*sp);
}

// ------------------------------- k_prep -------------------------------
__global__ void k_prep(const float* __restrict__ pw, const float* __restrict__ prew,
                       const float* __restrict__ qw, const float* __restrict__ g1,
                       const float* __restrict__ postw, const float* __restrict__ poutw)
{
  int t = blockIdx.x*256 + threadIdx.x;
  int nt = gridDim.x*256;
  for (int i=t; i<128*128; i+=nt){ int o=i>>7, c=i&127; g_projT[c*128+o]=pw[i]; g_poutT[c*128+o]=poutw[i]; }
  for (int i=t; i<64*64;  i+=nt){ int o=i>>6, c=i&63;  g_preT[c*64+o]=prew[i]; g_postT[c*64+o]=postw[i]; }
  for (int i=t; i<192*64; i+=nt){ int o=i/64, c=i%64;  g_qkvT[(o>>6)*4096 + c*64 + (o&63)] = qw[i]; }
  for (int i=t; i<32*64;  i+=nt){ int o=i>>6, c=i&63;  g_g1T[c*32+o]=g1[i]; }
  if (t < 256){ g_pooled[t]=0.0; g_qss[t]=0.0; g_kss[t]=0.0; }
  for (int i=t; i<2048; i+=nt) g_gram[i]=0.0;
  if (t < 32) g_resp_sum[t]=0.0;
  if (t == 0) g_gate_sum=0.0;
}

// ------------------------------- k_front: proj + pre + gate + qkv -------------------------------
#define FR_XS   8192
#define FR_SP   (8192 + 128*132)   // 25088
#define FR_TOT  (25088 + 512)      // 25600 floats = 100 KB -> 2 CTA/SM

__global__ void __launch_bounds__(256,2) k_front(
    const float* __restrict__ x, const float* __restrict__ pre_b,
    const float* __restrict__ gate_b1, const float* __restrict__ gate_w2,
    const float* __restrict__ gate_b2)
{
  extern __shared__ float sm[];
  float* ws    = sm;
  float* xs    = sm + FR_XS;
  float* spool = sm + FR_SP;
  int tid = threadIdx.x;
  int b   = blockIdx.x >> 9;
  int pb  = (blockIdx.x & 511) << 7;
  int oi  = tid & 31;
  int pg  = tid >> 5;       // 0..7 (warp-constant)
  int px0 = pg << 4;

  // load x tile
  const float* xb = x + (size_t)b*128*HW + pb;
  for (int i=tid; i<128*32; i+=256){
    int ch=i>>5, q=i&31;
    ((float4*)(xs + ch*132))[q] = __ldg((const float4*)(xb + (size_t)ch*HW) + q);
  }

  // ---- input_proj, 2 K-chunks ----
  u64 acc[4][8];
  #pragma unroll
  for (int i=0;i<4;i++){
    #pragma unroll
    for (int j=0;j<8;j++) acc[i][j]=0ull;
  }
  #pragma unroll
  for (int c=0;c<2;c++){
    __syncthreads();
    for (int i=tid; i<64*32; i+=256) ((float4*)ws)[i] = ((const float4*)(g_projT + c*8192))[i];
    __syncthreads();
    for (int kk=0; kk<64; kk++){
      const ulonglong2* xr = (const ulonglong2*)(xs + (c*64+kk)*132 + px0);
      ulonglong2 x01 = xr[0], x23 = xr[1], x45 = xr[2], x67 = xr[3];
      u64 xv[8] = {x01.x,x01.y,x23.x,x23.y,x45.x,x45.y,x67.x,x67.y};
      const float* wrow = ws + kk*128;
      #pragma unroll
      for (int i=0;i<4;i++){
        float w = wrow[oi + 32*i];
        u64 wp = pk2(w,w);
        #pragma unroll
        for (int j=0;j<8;j++) fma2(acc[i][j], wp, xv[j]);
      }
    }
  }
  __syncthreads();   // all xs reads done
  #pragma unroll
  for (int i=0;i<4;i++){
    ulonglong2* dst = (ulonglong2*)(xs + (oi+32*i)*132 + px0);
    #pragma unroll
    for (int m=0;m<4;m++){ ulonglong2 v; v.x=acc[i][2*m]; v.y=acc[i][2*m+1]; dst[m]=v; }
  }
  __syncthreads();

  // ---- store lb; load preT ----
  {
    float* lbp = g_lb + (size_t)b*64*HW + pb;
    for (int i=tid; i<64*32; i+=256){
      int ch=i>>5, q=i&31;
      *((float4*)(lbp + (size_t)ch*HW) + q) = ((const float4*)(xs + ch*132))[q];
    }
    for (int i=tid; i<64*16; i+=256) ((float4*)ws)[i] = ((const float4*)g_preT)[i];
  }
  __syncthreads();

  // ---- lgce pre conv (reads rows 0..63, writes rows 0..63 after reads) ----
  {
    u64 a2[2][8];
    #pragma unroll
    for (int i=0;i<2;i++){
      #pragma unroll
      for (int j=0;j<8;j++) a2[i][j]=0ull;
    }
    for (int k=0; k<64; k++){
      const ulonglong2* xr = (const ulonglong2*)(xs + k*132 + px0);
      ulonglong2 x01 = xr[0], x23 = xr[1], x45 = xr[2], x67 = xr[3];
      u64 xv[8] = {x01.x,x01.y,x23.x,x23.y,x45.x,x45.y,x67.x,x67.y};
      const float* wrow = ws + k*64;
      #pragma unroll
      for (int i=0;i<2;i++){
        float w = wrow[oi + 32*i];
        u64 wp = pk2(w,w);
        #pragma unroll
        for (int j=0;j<8;j++) fma2(a2[i][j], wp, xv[j]);
      }
    }
    __syncthreads();   // all reads of rows 0..63 done
    #pragma unroll
    for (int i=0;i<2;i++){
      int o = oi + 32*i;
      float bb = __ldg(pre_b + o);
      float psum = 0.f;
      float* dst = xs + o*132 + px0;
      #pragma unroll
      for (int j=0;j<8;j++){
        float2 v = upk2(a2[i][j]);
        v.x += bb; v.y += bb;
        psum += v.x + v.y;
        *((float2*)(dst + 2*j)) = v;
      }
      spool[o*8 + pg] = psum;
    }
  }
  __syncthreads();

  // ---- store xpre + pooled; load g1T ----
  {
    float* xpp = g_xpre + (size_t)b*64*HW + pb;
    for (int i=tid; i<64*32; i+=256){
      int ch=i>>5, q=i&31;
      *((float4*)(xpp + (size_t)ch*HW) + q) = ((const float4*)(xs + ch*132))[q];
    }
    if (tid < 64){
      float s = 0.f;
      #pragma unroll
      for (int t2=0;t2<8;t2++) s += spool[tid*8 + t2];
      atomicAdd(&g_pooled[b*64 + tid], (double)s);
    }
    for (int i=tid; i<64*8; i+=256) ((float4*)ws)[i] = ((const float4*)g_g1T)[i];
  }
  __syncthreads();

  // ---- gate hidden ----
  {
    float* hid = ws + 2048;   // 128*33
    int px = tid & 127;
    int o0 = (tid >> 7) << 4;
    u64 ga[8];
    #pragma unroll
    for (int i=0;i<8;i++) ga[i]=0ull;
    #pragma unroll 4
    for (int k=0;k<64;k++){
      float xv = xs[(64+k)*132 + px];
      u64 xp = pk2(xv,xv);
      const float4* wr = (const float4*)(ws + k*32 + o0);
      float4 w0 = wr[0], w1 = wr[1], w2v = wr[2], w3 = wr[3];
      fma2(ga[0], pk2(w0.x,w0.y), xp);
      fma2(ga[1], pk2(w0.z,w0.w), xp);
      fma2(ga[2], pk2(w1.x,w1.y), xp);
      fma2(ga[3], pk2(w1.z,w1.w), xp);
      fma2(ga[4], pk2(w2v.x,w2v.y), xp);
      fma2(ga[5], pk2(w2v.z,w2v.w), xp);
      fma2(ga[6], pk2(w3.x,w3.y), xp);
      fma2(ga[7], pk2(w3.z,w3.w), xp);
    }
    #pragma unroll
    for (int i=0;i<8;i++){
      float2 v = upk2(ga[i]);
      hid[px*33 + o0 + 2*i]     = fmaxf(v.x + __ldg(gate_b1 + o0 + 2*i), 0.f);
      hid[px*33 + o0 + 2*i + 1] = fmaxf(v.y + __ldg(gate_b1 + o0 + 2*i + 1), 0.f);
    }
  }
  __syncthreads();
  if (tid < 128){
    const float* hid = ws + 2048;
    float g = __ldg(gate_b2);
    #pragma unroll
    for (int h=0;h<32;h++) g = fmaf(hid[tid*33+h], __ldg(gate_w2+h), g);
    g = sigm(g);
    #pragma unroll
    for (int off=16; off; off>>=1) g += __shfl_down_sync(0xffffffffu, g, off);
    if ((tid&31)==0) atomicAdd(&g_gate_sum, (double)g);
  }

  // ---- qkv: 3 out-chunks of 64, staging in rows 0..63 ----
  float* qp = g_qkv + (size_t)b*192*HW + pb;
  for (int cc=0; cc<3; cc++){
    __syncthreads();   // hid reads / prior stage-store reads done
    for (int i=tid; i<64*16; i+=256) ((float4*)ws)[i] = ((const float4*)(g_qkvT + cc*4096))[i];
    __syncthreads();
    u64 a2[2][8];
    #pragma unroll
    for (int i=0;i<2;i++){
      #pragma unroll
      for (int j=0;j<8;j++) a2[i][j]=0ull;
    }
    for (int k=0; k<64; k++){
      const ulonglong2* xr = (const ulonglong2*)(xs + (64+k)*132 + px0);
      ulonglong2 x01 = xr[0], x23 = xr[1], x45 = xr[2], x67 = xr[3];
      u64 xv[8] = {x01.x,x01.y,x23.x,x23.y,x45.x,x45.y,x67.x,x67.y};
      const float* wrow = ws + k*64;
      #pragma unroll
      for (int i=0;i<2;i++){
        float w = wrow[oi + 32*i];
        u64 wp = pk2(w,w);
        #pragma unroll
        for (int j=0;j<8;j++) fma2(a2[i][j], wp, xv[j]);
      }
    }
    // stage into rows 0..63 (disjoint from compute reads; prior readers synced)
    #pragma unroll
    for (int i=0;i<2;i++){
      ulonglong2* dst = (ulonglong2*)(xs + (oi+32*i)*132 + px0);
      #pragma unroll
      for (int m=0;m<4;m++){ ulonglong2 v; v.x=a2[i][2*m]; v.y=a2[i][2*m+1]; dst[m]=v; }
    }
    __syncthreads();
    for (int t=tid; t<64*32; t+=256){
      int ch=t>>5, q=t&31;
      *((float4*)(qp + (size_t)(cc*64+ch)*HW) + q) = ((const float4*)(xs + ch*132))[q];
    }
  }
}

// ------------------------------- k_dw: depthwise 3x3 SAME, V ONLY -------------------------------
__global__ void __launch_bounds__(256) k_dw(const float* __restrict__ dww)
{
  int bid = blockIdx.x;                 // 256 * 64
  int bcv = bid >> 6;                   // b*64 + cv
  int bb  = bcv >> 6, cv = bcv & 63;
  int ch  = 128 + cv;
  int y   = ((bid & 63) << 2) + (threadIdx.x >> 6);
  int xq  = (threadIdx.x & 63) << 2;
  float w[9];
  #pragma unroll
  for (int i=0;i<9;i++) w[i] = __ldg(dww + ch*9 + i);
  const float* img = g_qkv + (size_t)(bb*192 + ch)*HW;
  float v[3][6];
  #pragma unroll
  for (int r=0;r<3;r++){
    int yy = y - 1 + r;
    if ((unsigned)yy < 256u){
      float4 c4 = __ldg((const float4*)(img + yy*IMW + xq));
      v[r][1]=c4.x; v[r][2]=c4.y; v[r][3]=c4.z; v[r][4]=c4.w;
      v[r][0] = (xq > 0)   ? __ldg(img + yy*IMW + xq - 1) : 0.f;
      v[r][5] = (xq < 252) ? __ldg(img + yy*IMW + xq + 4) : 0.f;
    } else {
      #pragma unroll
      for (int j=0;j<6;j++) v[r][j]=0.f;
    }
  }
  float o[4];
  #pragma unroll
  for (int j=0;j<4;j++){
    float s=0.f;
    #pragma unroll
    for (int r=0;r<3;r++){
      s = fmaf(v[r][j],   w[r*3+0], s);
      s = fmaf(v[r][j+1], w[r*3+1], s);
      s = fmaf(v[r][j+2], w[r*3+2], s);
    }
    o[j]=s;
  }
  float4 ov = {o[0],o[1],o[2],o[3]};
  *((float4*)(g_vd + (size_t)(bb*64 + cv)*HW + y*IMW + xq)) = ov;
}

// ------------------------------- k_small -------------------------------
__global__ void k_small(const float* __restrict__ w1, const float* __restrict__ b1,
                        const float* __restrict__ w2, const float* __restrict__ b2)
{
  int t = threadIdx.x;
  if (t < 32){
    int b = t >> 3, g = t & 7;
    float pooled[8];
    #pragma unroll
    for (int c=0;c<8;c++) pooled[c] = (float)(g_pooled[b*64 + g*8 + c] * (1.0/65536.0));
    float h0 = b1[g*2+0], h1 = b1[g*2+1];
    #pragma unroll
    for (int c=0;c<8;c++){
      h0 = fmaf(pooled[c], w1[g*16 + 0*8 + c], h0);
      h1 = fmaf(pooled[c], w1[g*16 + 1*8 + c], h1);
    }
    h0 = fmaxf(h0, 0.f); h1 = fmaxf(h1, 0.f);
    #pragma unroll
    for (int c=0;c<8;c++){
      float v = b2[g*8+c];
      v = fmaf(h0, w2[g*16 + c*2 + 0], v);
      v = fmaf(h1, w2[g*16 + c*2 + 1], v);
      g_cw[b*64 + g*8 + c] = sigm(v);
    }
    if (t == 0){
      float mean = (float)(g_gate_sum * (1.0/262144.0));
      g_kdyn = fminf(fmaxf(floorf(8.f*mean), 1.f), 8.f);
    }
  }
}

// ------------------------------- k_thr: 1 px/thread, 1024 blocks --------------
__global__ void __launch_bounds__(256) k_thr(const float* __restrict__ sw, const float* __restrict__ sb)
{
  __shared__ float cw_s[64], sw_s[64], sb_s[8];
  __shared__ float ssum[8];
  int tid = threadIdx.x;
  int b = blockIdx.x >> 8;
  int p = ((blockIdx.x & 255) << 8) + tid;
  if (tid < 64){ cw_s[tid] = g_cw[b*64 + tid]; sw_s[tid] = __ldg(sw + tid); }
  if (tid < 8){ sb_s[tid] = __ldg(sb + tid); ssum[tid] = 0.f; }
  __syncthreads();
  const float* xp = g_xpre + (size_t)b*64*HW + p;
  #pragma unroll
  for (int g=0; g<8; g++){
    float xv[8], resp[8];
    #pragma unroll
    for (int c=0;c<8;c++) xv[c] = __ldg(xp + (size_t)(g*8+c)*HW);
    group_resp(xv, cw_s + g*8, sw_s + g*8, sb_s[g], resp);
    float s = 0.f;
    #pragma unroll
    for (int c=0;c<8;c++) s += resp[c];
    #pragma unroll
    for (int off=16; off; off>>=1) s += __shfl_down_sync(0xffffffffu, s, off);
    if ((tid&31)==0) atomicAdd(&ssum[g], s);
  }
  __syncthreads();
  if (tid < 8) atomicAdd(&g_resp_sum[b*8 + tid], (double)ssum[tid]);
}

// ------------------------------- k_gram: fused dwconv(q,k) + Gram (R11 form) --------------------
#define GM_WDW  (16*792)            // 12672
#define GM_WRED (12672 + 160)       // 12832
#define GM_TOT  (12832 + 640)       // 13472 floats = 53.9 KB

__global__ void __launch_bounds__(256) k_gram(const float* __restrict__ dww)
{
  extern __shared__ float sm[];
  float* sbuf = sm;
  float* wdw  = sm + GM_WDW;
  float* wred = sm + GM_WRED;
  int tid = threadIdx.x;
  int bh    = blockIdx.x >> 5;
  int strip = blockIdx.x & 31;
  int b = bh >> 3, h = bh & 7;
  int r0 = strip << 3;

  if (tid < 144){
    int c = tid/9, j = tid%9;
    int ch = (c<8) ? (h*8+c) : (64 + h*8 + (c-8));
    wdw[tid] = __ldg(dww + ch*9 + j);
  }

  auto load_row = [&](int ry){
    int s = ((ry % 3) + 3) % 3;
    for (int i=tid; i<1024; i+=256){
      int c = i>>6, q = i&63;
      float4 v = {0.f,0.f,0.f,0.f};
      if ((unsigned)ry < 256u){
        int ch = (c<8) ? (h*8+c) : (64 + h*8 + (c-8));
        v = __ldg((const float4*)(g_qkv + (size_t)(b*192+ch)*HW + ry*IMW) + q);
      }
      *((float4*)(sbuf + c*792 + s*264 + 4 + 4*q)) = v;
    }
    if (tid < 32){
      int c = tid>>1, side = tid&1;
      sbuf[c*792 + s*264 + (side ? 260 : 3)] = 0.f;
    }
  };

  float gr[8][8], qs[8], ks[8];
  #pragma unroll
  for (int c=0;c<8;c++){
    qs[c]=0.f; ks[c]=0.f;
    #pragma unroll
    for (int d=0;d<8;d++) gr[c][d]=0.f;
  }

  load_row(r0-1);
  load_row(r0);
  int col = tid;
  for (int y=r0; y<r0+8; y++){
    load_row(y+1);
    __syncthreads();
    int s0 = ((y-1)%3 + 3)%3, s1 = y%3, s2 = (y+1)%3;
    int srow[3] = {s0, s1, s2};
    float q[8], k[8];
    #pragma unroll
    for (int c=0;c<8;c++){
      float aq = 0.f, ak = 0.f;
      #pragma unroll
      for (int r=0;r<3;r++){
        const float* pq = sbuf + c*792     + srow[r]*264 + 3 + col;
        const float* pk = sbuf + (8+c)*792 + srow[r]*264 + 3 + col;
        const float* wq = wdw + c*9 + r*3;
        const float* wk = wdw + 72 + c*9 + r*3;
        aq = fmaf(pq[0], wq[0], aq); aq = fmaf(pq[1], wq[1], aq); aq = fmaf(pq[2], wq[2], aq);
        ak = fmaf(pk[0], wk[0], ak); ak = fmaf(pk[1], wk[1], ak); ak = fmaf(pk[2], wk[2], ak);
      }
      q[c]=aq; k[c]=ak;
    }
    #pragma unroll
    for (int c=0;c<8;c++){
      qs[c]=fmaf(q[c],q[c],qs[c]); ks[c]=fmaf(k[c],k[c],ks[c]);
      #pragma unroll
      for (int d=0;d<8;d++) gr[c][d]=fmaf(q[c],k[d],gr[c][d]);
    }
    __syncthreads();
  }

  int lane = tid & 31, wd = tid >> 5;
  #pragma unroll
  for (int c=0;c<8;c++){
    #pragma unroll
    for (int d=0;d<8;d++){
      float v = gr[c][d];
      #pragma unroll
      for (int o=16;o;o>>=1) v += __shfl_down_sync(0xffffffffu, v, o);
      if (lane==0) wred[wd*80 + c*8 + d] = v;
    }
  }
  #pragma unroll
  for (int c=0;c<8;c++){
    float v = qs[c];
    #pragma unroll
    for (int o=16;o;o>>=1) v += __shfl_down_sync(0xffffffffu, v, o);
    if (lane==0) wred[wd*80 + 64 + c] = v;
    float u = ks[c];
    #pragma unroll
    for (int o=16;o;o>>=1) u += __shfl_down_sync(0xffffffffu, u, o);
    if (lane==0) wred[wd*80 + 72 + c] = u;
  }
  __syncthreads();
  if (tid < 80){
    float s = 0.f;
    #pragma unroll
    for (int ww=0; ww<8; ww++) s += wred[ww*80 + tid];
    if (tid < 64)      atomicAdd(&g_gram[(b*8+h)*64 + tid], (double)s);
    else if (tid < 72) atomicAdd(&g_qss[b*64 + h*8 + (tid-64)], (double)s);
    else               atomicAdd(&g_kss[b*64 + h*8 + (tid-72)], (double)s);
  }
}

// ------------------------------- k_attn -------------------------------
__global__ void k_attn(const float* __restrict__ temp, const float* __restrict__ scales)
{
  int t = threadIdx.x;
  if (t >= 32) return;
  int b = t >> 3, h = t & 7;
  float scl = scales[0] + scales[1] + scales[2] + scales[3];
  float T   = temp[h];
  float kd  = g_kdyn;
  float nq[8], nk[8];
  #pragma unroll
  for (int c=0;c<8;c++){
    nq[c] = fmaxf(sqrtf((float)g_qss[b*64 + h*8 + c]), 1e-12f);
    nk[c] = fmaxf(sqrtf((float)g_kss[b*64 + h*8 + c]), 1e-12f);
  }
  float a[8][8];
  #pragma unroll
  for (int c=0;c<8;c++){
    #pragma unroll
    for (int d=0;d<8;d++)
      a[c][d] = ((float)g_gram[(b*8+h)*64 + c*8 + d]) / (nq[c]*nk[d]) * T;
  }
  #pragma unroll
  for (int c=0;c<8;c++){
    bool keep[8];
    #pragma unroll
    for (int d=0;d<8;d++){
      int r = 0;
      #pragma unroll
      for (int e=0;e<8;e++)
        r += (a[c][e] > a[c][d]) || (a[c][e] == a[c][d] && e < d);
      keep[d] = ((float)r < kd);
    }
    float m = -1e30f;
    #pragma unroll
    for (int d=0;d<8;d++) if (keep[d]) m = fmaxf(m, a[c][d]);
    float pr[8]; float sum = 0.f;
    #pragma unroll
    for (int d=0;d<8;d++){ pr[d] = keep[d] ? __expf(a[c][d]-m) : 0.f; sum += pr[d]; }
    float inv = scl / sum;
    #pragma unroll
    for (int d=0;d<8;d++) g_attnw[((b*8+h)*8 + c)*8 + d] = pr[d]*inv;
  }
}

// ------------------------------- k_final: 128-px tiles, 512 threads, 2 CTA/SM ------------------
// wb halved to 8192 floats; proj_out weights loaded in 2 k-chunks.
#define FN_XS  8192
#define FN_VB  (8192 + 64*132)           // 16640
#define FN_WS  (16640 + 64*132)          // 25088
#define FN_CW  (25088 + 512)             // 25600
#define FN_THR (25600 + 64)              // 25664
#define FN_TOT (25664 + 8)               // 25672 floats = 102.7 KB -> 2 CTA/SM (32 warps)

__global__ void __launch_bounds__(512,2) k_final(
    const float* __restrict__ sw, const float* __restrict__ sb,
    const float* __restrict__ post_b, float* __restrict__ out)
{
  extern __shared__ float sm[];
  float* wb    = sm;
  float* xs    = sm + FN_XS;
  float* vb    = sm + FN_VB;
  float* W_s   = sm + FN_WS;
  float* cw_s  = sm + FN_CW;
  float* thr_s = sm + FN_THR;

  int tid = threadIdx.x;
  int b   = blockIdx.x >> 9;
  int pb  = (blockIdx.x & 511) << 7;
  int oi  = tid & 63;
  int qg  = tid >> 6;        // 0..7 (warp-pair constant)
  int px0 = qg << 4;

  for (int i=tid; i<1024; i+=512) ((float4*)wb)[i] = ((const float4*)g_postT)[i];
  for (int i=tid; i<512;  i+=512) W_s[i] = g_attnw[b*512 + i];
  if (tid < 64) cw_s[tid] = g_cw[b*64 + tid];
  if (tid < 8)  thr_s[tid] = (float)(g_resp_sum[b*8 + tid] * (1.0/524288.0));
  {
    const float* xp  = g_xpre + (size_t)b*64*HW + pb;
    const float* lbp = g_lb   + (size_t)b*64*HW + pb;
    for (int i=tid; i<64*32; i+=512){
      int ch=i>>5, q=i&31;
      ((float4*)(xs + ch*132))[q] = __ldg((const float4*)(xp  + (size_t)ch*HW) + q);
      ((float4*)(vb + ch*132))[q] = __ldg((const float4*)(lbp + (size_t)ch*HW) + q);
    }
  }
  __syncthreads();

  // mask in place (same group_resp as k_thr): 128 px x 8 groups / 512 threads
  {
    int p  = tid & 127;
    int g0 = (tid >> 7) << 1;
    #pragma unroll
    for (int gi=0; gi<2; gi++){
      int g = g0 + gi;
      float xv[8], resp[8], sw8[8];
      #pragma unroll
      for (int c=0;c<8;c++){ xv[c] = xs[(g*8+c)*132 + p]; sw8[c] = __ldg(sw + g*8 + c); }
      group_resp(xv, cw_s + g*8, sw8, __ldg(sb + g), resp);
      float thr = thr_s[g];
      #pragma unroll
      for (int c=0;c<8;c++){
        float m = resp[c] > thr ? 1.f : resp[c];
        xs[(g*8+c)*132 + p] = xv[c]*m;
      }
    }
  }
  __syncthreads();

  // post conv: out oi x 16 px, K=64; + bias + residual (vb = lb)
  float pres[16];
  {
    u64 pa[8];
    #pragma unroll
    for (int j=0;j<8;j++) pa[j]=0ull;
    for (int k=0; k<64; k++){
      const ulonglong2* xr = (const ulonglong2*)(xs + k*132 + px0);
      ulonglong2 x01 = xr[0], x23 = xr[1], x45 = xr[2], x67 = xr[3];
      u64 xv[8] = {x01.x,x01.y,x23.x,x23.y,x45.x,x45.y,x67.x,x67.y};
      float w = wb[k*64 + oi];
      u64 wp = pk2(w,w);
      #pragma unroll
      for (int j=0;j<8;j++) fma2(pa[j], wp, xv[j]);
    }
    float bb = __ldg(post_b + oi);
    const float* rr = vb + oi*132 + px0;
    #pragma unroll
    for (int j=0;j<8;j++){
      float2 v = upk2(pa[j]);
      pres[2*j]   = v.x + bb + rr[2*j];
      pres[2*j+1] = v.y + bb + rr[2*j+1];
    }
  }
  __syncthreads();
  {
    float* dst = xs + oi*132 + px0;
    #pragma unroll
    for (int j=0;j<8;j++) *((float2*)(dst + 2*j)) = make_float2(pres[2*j], pres[2*j+1]);
    const float* vp = g_vd + (size_t)b*64*HW + pb;
    for (int i=tid; i<64*32; i+=512){
      int ch=i>>5, q=i&31;
      ((float4*)(vb + ch*132))[q] = __ldg((const float4*)(vp + (size_t)ch*HW) + q);
    }
  }
  __syncthreads();

  // attn mix: out oi (head oi>>3), 16 px
  {
    int h = oi >> 3;
    u64 aa[8];
    #pragma unroll
    for (int j=0;j<8;j++) aa[j]=0ull;
    #pragma unroll
    for (int d=0;d<8;d++){
      float w = W_s[oi*8 + d];
      u64 wp = pk2(w,w);
      const ulonglong2* xr = (const ulonglong2*)(vb + (h*8+d)*132 + px0);
      ulonglong2 x01 = xr[0], x23 = xr[1], x45 = xr[2], x67 = xr[3];
      fma2(aa[0], wp, x01.x); fma2(aa[1], wp, x01.y);
      fma2(aa[2], wp, x23.x); fma2(aa[3], wp, x23.y);
      fma2(aa[4], wp, x45.x); fma2(aa[5], wp, x45.y);
      fma2(aa[6], wp, x67.x); fma2(aa[7], wp, x67.y);
    }
    __syncthreads();   // all vb reads done
    ulonglong2* dst = (ulonglong2*)(vb + oi*132 + px0);
    #pragma unroll
    for (int m=0;m<4;m++){ ulonglong2 v; v.x=aa[2*m]; v.y=aa[2*m+1]; dst[m]=v; }
    // load proj_out weight chunk A (rows 0..63)
    for (int i=tid; i<2048; i+=512) ((float4*)wb)[i] = ((const float4*)g_poutT)[i];
  }
  __syncthreads();

  // proj_out: outs (oi, oi+64) x 16 px, K=128 in 2 weight chunks
  {
    u64 po[2][8];
    #pragma unroll
    for (int i=0;i<2;i++){
      #pragma unroll
      for (int j=0;j<8;j++) po[i][j]=0ull;
    }
    // chunk A: k = 0..63 (attn rows in vb), weights rows 0..63 in wb
    for (int k=0; k<64; k++){
      const ulonglong2* xr = (const ulonglong2*)(vb + k*132 + px0);
      ulonglong2 x01 = xr[0], x23 = xr[1], x45 = xr[2], x67 = xr[3];
      u64 xv[8] = {x01.x,x01.y,x23.x,x23.y,x45.x,x45.y,x67.x,x67.y};
      const float* wrow = wb + k*128;
      #pragma unroll
      for (int i=0;i<2;i++){
        float w = wrow[oi + 64*i];
        u64 wp = pk2(w,w);
        #pragma unroll
        for (int j=0;j<8;j++) fma2(po[i][j], wp, xv[j]);
      }
    }
    __syncthreads();   // all chunk-A weight reads done
    for (int i=tid; i<2048; i+=512) ((float4*)wb)[i] = ((const float4*)g_poutT)[2048 + i];
    __syncthreads();
    // chunk B: k = 64..127 (post rows in xs), weights rows 64..127 in wb
    for (int k=0; k<64; k++){
      const ulonglong2* xr = (const ulonglong2*)(xs + k*132 + px0);
      ulonglong2 x01 = xr[0], x23 = xr[1], x45 = xr[2], x67 = xr[3];
      u64 xv[8] = {x01.x,x01.y,x23.x,x23.y,x45.x,x45.y,x67.x,x67.y};
      const float* wrow = wb + k*128;
      #pragma unroll
      for (int i=0;i<2;i++){
        float w = wrow[oi + 64*i];
        u64 wp = pk2(w,w);
        #pragma unroll
        for (int j=0;j<8;j++) fma2(po[i][j], wp, xv[j]);
      }
    }
    __syncthreads();   // all vb/xs reads done
    ulonglong2* d0 = (ulonglong2*)(vb + oi*132 + px0);
    ulonglong2* d1 = (ulonglong2*)(xs + oi*132 + px0);
    #pragma unroll
    for (int m=0;m<4;m++){
      ulonglong2 v0; v0.x=po[0][2*m]; v0.y=po[0][2*m+1]; d0[m]=v0;
      ulonglong2 v1; v1.x=po[1][2*m]; v1.y=po[1][2*m+1]; d1[m]=v1;
    }
  }
  __syncthreads();
  {
    float* op = out + (size_t)b*128*HW + pb;
    for (int i=tid; i<64*32; i+=512){
      int ch=i>>5, q=i&31;
      *((float4*)(op + (size_t)ch*HW) + q)      = ((const float4*)(vb + ch*132))[q];
      *((float4*)(op + (size_t)(64+ch)*HW) + q) = ((const float4*)(xs + ch*132))[q];
    }
  }
}

// ------------------------------- launch -------------------------------
extern "C" void kernel_launch(void* const* d_in, const int* in_sizes, int n_in,
                              void* d_out, int out_size)
{
  const float* x      = (const float*)d_in[0];
  const float* projw  = (const float*)d_in[1];
  const float* prew   = (const float*)d_in[2];
  const float* preb   = (const float*)d_in[3];
  const float* w1     = (const float*)d_in[4];
  const float* b1     = (const float*)d_in[5];
  const float* w2     = (const float*)d_in[6];
  const float* b2     = (const float*)d_in[7];
  const float* sw     = (const float*)d_in[8];
  const float* sb     = (const float*)d_in[9];
  const float* postw  = (const float*)d_in[10];
  const float* postb  = (const float*)d_in[11];
  const float* qkvw   = (const float*)d_in[12];
  const float* dww    = (const float*)d_in[13];
  const float* gw1    = (const float*)d_in[14];
  const float* gb1    = (const float*)d_in[15];
  const float* gw2    = (const float*)d_in[16];
  const float* gb2    = (const float*)d_in[17];
  const float* temp   = (const float*)d_in[18];
  const float* scales = (const float*)d_in[19];
  const float* poutw  = (const float*)d_in[20];
  float* out = (float*)d_out;

  cudaFuncSetAttribute(k_front, cudaFuncAttributeMaxDynamicSharedMemorySize, FR_TOT*4);
  cudaFuncSetAttribute(k_gram,  cudaFuncAttributeMaxDynamicSharedMemorySize, GM_TOT*4);
  cudaFuncSetAttribute(k_final, cudaFuncAttributeMaxDynamicSharedMemorySize, FN_TOT*4);

  // Fork/join across streams (capture-safe event pattern).
  cudaStream_t s1, s2;
  cudaStreamCreateWithFlags(&s1, cudaStreamNonBlocking);
  cudaStreamCreateWithFlags(&s2, cudaStreamNonBlocking);
  cudaEvent_t eF, e1, e2;
  cudaEventCreateWithFlags(&eF, cudaEventDisableTiming);
  cudaEventCreateWithFlags(&e1, cudaEventDisableTiming);
  cudaEventCreateWithFlags(&e2, cudaEventDisableTiming);

  k_prep <<<64, 256>>>(projw, prew, qkvw, gw1, postw, poutw);
  k_front<<<2048, 256, FR_TOT*4>>>(x, preb, gb1, gw2, gb2);
  cudaEventRecord(eF, 0);

  // s1: depthwise v-conv (needs g_qkv only)
  cudaStreamWaitEvent(s1, eF, 0);
  k_dw<<<256*64, 256, 0, s1>>>(dww);
  cudaEventRecord(e1, s1);

  // s2: fused q/k dwconv + gram (needs g_qkv only)
  cudaStreamWaitEvent(s2, eF, 0);
  k_gram<<<1024, 256, GM_TOT*4, s2>>>(dww);
  cudaEventRecord(e2, s2);

  // main: cw/kdyn then resp-threshold
  k_small<<<1, 32>>>(w1, b1, w2, b2);
  k_thr  <<<1024, 256>>>(sw, sb);

  // join: attn needs gram(+kdyn); final needs everything
  cudaStreamWaitEvent(0, e2, 0);
  k_attn <<<1, 32>>>(temp, scales);
  cudaStreamWaitEvent(0, e1, 0);
  k_final<<<2048, 512, FN_TOT*4>>>(sw, sb, postb, out);

  cudaEventDestroy(eF); cudaEventDestroy(e1); cudaEventDestroy(e2);
  cudaStreamDestroy(s1); cudaStreamDestroy(s2);
}